// round 1
// baseline (speedup 1.0000x reference)
#include <cuda_runtime.h>
#include <math.h>

#define S_LEN 2048
#define D_MODEL 2048
#define NUM_HEADS 16
#define DH 128
#define BATCH 2
#define M_TOT (BATCH * S_LEN)   // 4096

// Scratch (allocation-free rule: __device__ globals)
__device__ float g_Q[(size_t)M_TOT * D_MODEL];
__device__ float g_K[(size_t)M_TOT * D_MODEL];
__device__ float g_V[(size_t)M_TOT * D_MODEL];
__device__ float g_AO[(size_t)M_TOT * D_MODEL];

// ---------------------------------------------------------------------------
// SGEMM: C[M,N] = A[M,K] * op(B)
//   TRANS_B=true : C[m,n] = sum_k A[m,k] * B[n,k]   (B row-major [N,K])
//   TRANS_B=false: C[m,n] = sum_k A[m,k] * B[k,n]   (B row-major [K,N])
// Block tile 128x128, K-tile 16, 256 threads, 8x8 micro-tile.
// All dims are multiples of tile sizes for this problem -> no bounds checks.
// ---------------------------------------------------------------------------
template <bool TRANS_B>
__global__ __launch_bounds__(256)
void sgemm_kernel(const float* __restrict__ A, const float* __restrict__ B,
                  float* __restrict__ C, int M, int N, int K,
                  int lda, int ldb, int ldc)
{
    __shared__ float As[16][128];
    __shared__ float Bs[16][132];   // padded for float4-aligned NN stores

    const int tid = threadIdx.x;
    const int tx = tid & 15;
    const int ty = tid >> 4;
    const int m0 = blockIdx.y * 128;
    const int n0 = blockIdx.x * 128;

    float acc[8][8];
#pragma unroll
    for (int i = 0; i < 8; i++)
#pragma unroll
        for (int j = 0; j < 8; j++) acc[i][j] = 0.0f;

    for (int k0 = 0; k0 < K; k0 += 16) {
        // Load A tile (k-contiguous in gmem), store transposed As[k][m]
#pragma unroll
        for (int it = 0; it < 2; it++) {
            int idx = it * 256 + tid;          // 512 float4
            int m = idx >> 2, kq = idx & 3;
            float4 v = *(const float4*)&A[(size_t)(m0 + m) * lda + k0 + kq * 4];
            As[kq * 4 + 0][m] = v.x;
            As[kq * 4 + 1][m] = v.y;
            As[kq * 4 + 2][m] = v.z;
            As[kq * 4 + 3][m] = v.w;
        }
        if (TRANS_B) {
#pragma unroll
            for (int it = 0; it < 2; it++) {
                int idx = it * 256 + tid;
                int n = idx >> 2, kq = idx & 3;
                float4 v = *(const float4*)&B[(size_t)(n0 + n) * ldb + k0 + kq * 4];
                Bs[kq * 4 + 0][n] = v.x;
                Bs[kq * 4 + 1][n] = v.y;
                Bs[kq * 4 + 2][n] = v.z;
                Bs[kq * 4 + 3][n] = v.w;
            }
        } else {
#pragma unroll
            for (int it = 0; it < 2; it++) {
                int idx = it * 256 + tid;      // 512 float4: 16 k-rows x 32
                int k = idx >> 5, nq = idx & 31;
                float4 v = *(const float4*)&B[(size_t)(k0 + k) * ldb + n0 + nq * 4];
                *(float4*)&Bs[k][nq * 4] = v;
            }
        }
        __syncthreads();

#pragma unroll
        for (int kk = 0; kk < 16; kk++) {
            float a[8], b[8];
            *(float4*)&a[0] = *(float4*)&As[kk][ty * 8];
            *(float4*)&a[4] = *(float4*)&As[kk][ty * 8 + 4];
            *(float4*)&b[0] = *(float4*)&Bs[kk][tx * 8];
            *(float4*)&b[4] = *(float4*)&Bs[kk][tx * 8 + 4];
#pragma unroll
            for (int i = 0; i < 8; i++)
#pragma unroll
                for (int j = 0; j < 8; j++) acc[i][j] += a[i] * b[j];
        }
        __syncthreads();
    }

#pragma unroll
    for (int i = 0; i < 8; i++) {
        int m = m0 + ty * 8 + i;
#pragma unroll
        for (int j = 0; j < 8; j += 4) {
            float4 v = make_float4(acc[i][j], acc[i][j + 1], acc[i][j + 2], acc[i][j + 3]);
            *(float4*)&C[(size_t)m * ldc + n0 + tx * 8 + j] = v;
        }
    }
}

// ---------------------------------------------------------------------------
// RoPE: in-place on Q and K in [B,S,D] layout (head h occupies cols h*128..).
// One thread per (b,s,h,i) half-pair, i in [0,64). Accurate angle via double
// range reduction + sincospif (error ~1e-7, safely below 1e-3 tolerance).
// ---------------------------------------------------------------------------
__global__ __launch_bounds__(256)
void rope_kernel(float* __restrict__ Q, float* __restrict__ K)
{
    int idx = blockIdx.x * blockDim.x + threadIdx.x;   // B*S*H*64 = 2^22
    int i = idx & 63;
    int h = (idx >> 6) & 15;
    int s = (idx >> 10) & (S_LEN - 1);
    int b = idx >> 21;

    // inv_freq = 10000^{-2i/128} = 2^{-i * log2(10000)/64}
    double inv = exp2(-0.20762050593046937 * (double)i);
    double ang = (double)s * inv;
    double t = ang * 0.15915494309189535;   // /(2*pi)
    t -= floor(t);                          // frac in [0,1)
    float sn, cs;
    sincospif(2.0f * (float)t, &sn, &cs);

    size_t base = ((size_t)(b * S_LEN + s)) * D_MODEL + h * DH + i;
    float q1 = Q[base], q2 = Q[base + 64];
    Q[base]      = q1 * cs - q2 * sn;
    Q[base + 64] = q2 * cs + q1 * sn;
    float k1 = K[base], k2 = K[base + 64];
    K[base]      = k1 * cs - k2 * sn;
    K[base + 64] = k2 * cs + k1 * sn;
}

// ---------------------------------------------------------------------------
// Flash attention (causal), fp32. One block per (q-tile, b*h).
// BM=BN=64, dh=128, 256 threads.
// Smem (dynamic): Qs[64][128], Ks[64][132], Vs[64][128], Ps[64][68]
// Micro-tile maps chosen so inner-loop LDS are broadcast or conflict-free:
//   QK^T : rows r = ty+16i, cols c = tx+16j  (Ks stride 132 -> bank-clean)
//   PV   : cols  = tx*4+j (+64)              (V rows contiguous)
// ---------------------------------------------------------------------------
#define ATTN_SMEM_FLOATS (64*128 + 64*132 + 64*128 + 64*68)

__global__ __launch_bounds__(256)
void attn_kernel(const float* __restrict__ Q, const float* __restrict__ K,
                 const float* __restrict__ V, float* __restrict__ AO)
{
    extern __shared__ float sm[];
    float* Qs = sm;                  // 64*128
    float* Ks = Qs + 64 * 128;       // 64*132
    float* Vs = Ks + 64 * 132;       // 64*128
    float* Ps = Vs + 64 * 128;       // 64*68
    __shared__ float m_s[64], l_s[64], a_s[64];

    const int tid = threadIdx.x;
    const int tx = tid & 15;
    const int ty = tid >> 4;
    const int qt = blockIdx.x;                // 0..31
    const int bh = blockIdx.y;                // 0..31
    const int b = bh >> 4, h = bh & 15;
    const int q0 = qt * 64;
    const size_t head_off = (size_t)b * S_LEN * D_MODEL + (size_t)h * DH;
    const float scale = 0.08838834764831845f; // 1/sqrt(128)

    // Load Q tile (64 rows x 128)
#pragma unroll
    for (int it = 0; it < 8; it++) {
        int idx = it * 256 + tid;             // 2048 float4
        int r = idx >> 5, dq = idx & 31;
        float4 v = *(const float4*)&Q[head_off + (size_t)(q0 + r) * D_MODEL + dq * 4];
        *(float4*)&Qs[r * 128 + dq * 4] = v;
    }
    if (tid < 64) { m_s[tid] = -1e30f; l_s[tid] = 0.0f; }

    float o[4][8];
#pragma unroll
    for (int i = 0; i < 4; i++)
#pragma unroll
        for (int j = 0; j < 8; j++) o[i][j] = 0.0f;

    for (int kt = 0; kt <= qt; kt++) {
        const int k0 = kt * 64;
        __syncthreads();   // protect Ks/Vs reuse from previous iteration

        // Load K,V tiles
#pragma unroll
        for (int it = 0; it < 8; it++) {
            int idx = it * 256 + tid;
            int c = idx >> 5, dq = idx & 31;
            float4 kv = *(const float4*)&K[head_off + (size_t)(k0 + c) * D_MODEL + dq * 4];
            *(float4*)&Ks[c * 132 + dq * 4] = kv;
            float4 vv = *(const float4*)&V[head_off + (size_t)(k0 + c) * D_MODEL + dq * 4];
            *(float4*)&Vs[c * 128 + dq * 4] = vv;
        }
        __syncthreads();

        // --- S = Q K^T (4x4 micro-tile, rows ty+16i, cols tx+16j) ---
        float sacc[4][4];
#pragma unroll
        for (int i = 0; i < 4; i++)
#pragma unroll
            for (int j = 0; j < 4; j++) sacc[i][j] = 0.0f;

#pragma unroll 4
        for (int d = 0; d < 128; d += 4) {
            float4 kv[4];
#pragma unroll
            for (int j = 0; j < 4; j++)
                kv[j] = *(float4*)&Ks[(tx + 16 * j) * 132 + d];
#pragma unroll
            for (int i = 0; i < 4; i++) {
                float4 qv = *(float4*)&Qs[(ty + 16 * i) * 128 + d];
#pragma unroll
                for (int j = 0; j < 4; j++)
                    sacc[i][j] += qv.x * kv[j].x + qv.y * kv[j].y +
                                  qv.z * kv[j].z + qv.w * kv[j].w;
            }
        }

        // Scale + causal mask -> Ps
#pragma unroll
        for (int i = 0; i < 4; i++) {
            int r = ty + 16 * i, gq = q0 + r;
#pragma unroll
            for (int j = 0; j < 4; j++) {
                int c = tx + 16 * j;
                float v = sacc[i][j] * scale;
                if (k0 + c > gq) v = -1e30f;
                Ps[r * 68 + c] = v;
            }
        }
        __syncthreads();

        // --- Online softmax: 4 threads per row, 16 elems each ---
        {
            int r = tid >> 2;
            int seg = (tid & 3) * 16;
            float4 vv[4];
            float mx = -1e30f;
#pragma unroll
            for (int k = 0; k < 4; k++) {
                vv[k] = *(float4*)&Ps[r * 68 + seg + k * 4];
                mx = fmaxf(mx, fmaxf(fmaxf(vv[k].x, vv[k].y), fmaxf(vv[k].z, vv[k].w)));
            }
            mx = fmaxf(mx, __shfl_xor_sync(0xffffffffu, mx, 1));
            mx = fmaxf(mx, __shfl_xor_sync(0xffffffffu, mx, 2));
            float m_old = m_s[r];
            float m_new = fmaxf(m_old, mx);
            float sum = 0.0f;
#pragma unroll
            for (int k = 0; k < 4; k++) {
                vv[k].x = __expf(vv[k].x - m_new);
                vv[k].y = __expf(vv[k].y - m_new);
                vv[k].z = __expf(vv[k].z - m_new);
                vv[k].w = __expf(vv[k].w - m_new);
                sum += vv[k].x + vv[k].y + vv[k].z + vv[k].w;
                *(float4*)&Ps[r * 68 + seg + k * 4] = vv[k];
            }
            sum += __shfl_xor_sync(0xffffffffu, sum, 1);
            sum += __shfl_xor_sync(0xffffffffu, sum, 2);
            if ((tid & 3) == 0) {
                float a = __expf(m_old - m_new);
                a_s[r] = a;
                m_s[r] = m_new;
                l_s[r] = l_s[r] * a + sum;
            }
        }
        __syncthreads();

        // --- Rescale O, then O += P @ V ---
        float al[4];
#pragma unroll
        for (int i = 0; i < 4; i++) al[i] = a_s[ty + 16 * i];
#pragma unroll
        for (int i = 0; i < 4; i++)
#pragma unroll
            for (int j = 0; j < 8; j++) o[i][j] *= al[i];

#pragma unroll 2
        for (int kk = 0; kk < 64; kk += 4) {
            float4 pv[4];
#pragma unroll
            for (int i = 0; i < 4; i++)
                pv[i] = *(float4*)&Ps[(ty + 16 * i) * 68 + kk];
#pragma unroll
            for (int u = 0; u < 4; u++) {
                float4 v0 = *(float4*)&Vs[(kk + u) * 128 + tx * 4];
                float4 v1 = *(float4*)&Vs[(kk + u) * 128 + 64 + tx * 4];
#pragma unroll
                for (int i = 0; i < 4; i++) {
                    float p = (u == 0) ? pv[i].x : (u == 1) ? pv[i].y
                             : (u == 2) ? pv[i].z : pv[i].w;
                    o[i][0] += p * v0.x; o[i][1] += p * v0.y;
                    o[i][2] += p * v0.z; o[i][3] += p * v0.w;
                    o[i][4] += p * v1.x; o[i][5] += p * v1.y;
                    o[i][6] += p * v1.z; o[i][7] += p * v1.w;
                }
            }
        }
    }

    // Epilogue: normalize and store
#pragma unroll
    for (int i = 0; i < 4; i++) {
        int r = ty + 16 * i;
        float inv = 1.0f / l_s[r];
        size_t rowp = head_off + (size_t)(q0 + r) * D_MODEL;
        float4 w0 = make_float4(o[i][0] * inv, o[i][1] * inv, o[i][2] * inv, o[i][3] * inv);
        float4 w1 = make_float4(o[i][4] * inv, o[i][5] * inv, o[i][6] * inv, o[i][7] * inv);
        *(float4*)&AO[rowp + tx * 4] = w0;
        *(float4*)&AO[rowp + 64 + tx * 4] = w1;
    }
}

// ---------------------------------------------------------------------------
extern "C" void kernel_launch(void* const* d_in, const int* in_sizes, int n_in,
                              void* d_out, int out_size)
{
    const float* x   = (const float*)d_in[0];
    const float* wq  = (const float*)d_in[1];
    const float* wkv = (const float*)d_in[2];
    const float* wo  = (const float*)d_in[3];
    float* out = (float*)d_out;

    float *Q, *K, *V, *AO;
    cudaGetSymbolAddress((void**)&Q,  g_Q);
    cudaGetSymbolAddress((void**)&K,  g_K);
    cudaGetSymbolAddress((void**)&V,  g_V);
    cudaGetSymbolAddress((void**)&AO, g_AO);

    dim3 blk(256);

    // Q = x @ wq^T   (NT)
    sgemm_kernel<true><<<dim3(D_MODEL / 128, M_TOT / 128), blk>>>(
        x, wq, Q, M_TOT, D_MODEL, D_MODEL, D_MODEL, D_MODEL, D_MODEL);
    // K = x @ wkv[:, :2048]   (NN, ldb = 4096)
    sgemm_kernel<false><<<dim3(D_MODEL / 128, M_TOT / 128), blk>>>(
        x, wkv, K, M_TOT, D_MODEL, D_MODEL, D_MODEL, 2 * D_MODEL, D_MODEL);
    // V = x @ wkv[:, 2048:]
    sgemm_kernel<false><<<dim3(D_MODEL / 128, M_TOT / 128), blk>>>(
        x, wkv + D_MODEL, V, M_TOT, D_MODEL, D_MODEL, D_MODEL, 2 * D_MODEL, D_MODEL);

    // RoPE in place on Q, K
    rope_kernel<<<(BATCH * S_LEN * NUM_HEADS * 64) / 256, blk>>>(Q, K);

    // Flash attention
    static const int attn_smem = ATTN_SMEM_FLOATS * (int)sizeof(float);
    cudaFuncSetAttribute(attn_kernel, cudaFuncAttributeMaxDynamicSharedMemorySize,
                         attn_smem);
    attn_kernel<<<dim3(S_LEN / 64, BATCH * NUM_HEADS), blk, attn_smem>>>(Q, K, V, AO);

    // out = AO @ wo^T  (NT)
    sgemm_kernel<true><<<dim3(D_MODEL / 128, M_TOT / 128), blk>>>(
        AO, wo, out, M_TOT, D_MODEL, D_MODEL, D_MODEL, D_MODEL, D_MODEL);
}

// round 2
// speedup vs baseline: 2.0282x; 2.0282x over previous
#include <cuda_runtime.h>
#include <math.h>
#include <stdint.h>

#define S_LEN 2048
#define D_MODEL 2048
#define NUM_HEADS 16
#define DH 128
#define BATCH 2
#define M_TOT (BATCH * S_LEN)   // 4096

// Scratch (allocation-free rule: __device__ globals)
__device__ float g_Q[(size_t)M_TOT * D_MODEL];
__device__ float g_K[(size_t)M_TOT * D_MODEL];
__device__ float g_V[(size_t)M_TOT * D_MODEL];
__device__ float g_AO[(size_t)M_TOT * D_MODEL];

// ---------------------------------------------------------------------------
// TF32 helpers
// ---------------------------------------------------------------------------
__device__ __forceinline__ uint32_t f2tf(float x) {
    uint32_t u;
    asm("cvt.rna.tf32.f32 %0, %1;" : "=r"(u) : "f"(x));
    return u;
}

__device__ __forceinline__ void mma_tf32(float* c, const uint32_t* a, const uint32_t* b) {
    asm volatile(
        "mma.sync.aligned.m16n8k8.row.col.f32.tf32.tf32.f32 "
        "{%0,%1,%2,%3}, {%4,%5,%6,%7}, {%8,%9}, {%0,%1,%2,%3};"
        : "+f"(c[0]), "+f"(c[1]), "+f"(c[2]), "+f"(c[3])
        : "r"(a[0]), "r"(a[1]), "r"(a[2]), "r"(a[3]), "r"(b[0]), "r"(b[1]));
}

// ---------------------------------------------------------------------------
// TF32 tensor-core GEMM: C[M,N] = A[M,K] * op(B), fp32 accumulate.
//   TRANS_B=true : C[m,n] = sum_k A[m,k] * B[n,k]   (B row-major [N,K])
//   TRANS_B=false: C[m,n] = sum_k A[m,k] * B[k,n]   (B row-major [K,N])
// Block 128x128, k-tile 32, 256 threads (8 warps as 2m x 4n), warp tile 64x32.
// mma.m16n8k8: 4 m-atoms x 4 n-atoms per warp.
// Smem strides: 36 (k-major, fragment reads land on banks 4r+cq -> all 32
// distinct), 136 for NN B (banks 8cq+r -> all 32 distinct).
// All dims are multiples of tile sizes -> no bounds checks.
// ---------------------------------------------------------------------------
template <bool TRANS_B>
__global__ __launch_bounds__(256)
void tf32_gemm(const float* __restrict__ A, const float* __restrict__ B,
               float* __restrict__ C, int M, int N, int K,
               int lda, int ldb, int ldc)
{
    __shared__ uint32_t As[128 * 36];
    __shared__ uint32_t Bs[TRANS_B ? (128 * 36) : (32 * 136)];

    const int tid  = threadIdx.x;
    const int lane = tid & 31;
    const int wid  = tid >> 5;
    const int wm   = (wid >> 2) * 64;   // warp m offset within block
    const int wn   = (wid & 3) * 32;    // warp n offset within block
    const int m0   = blockIdx.y * 128;
    const int n0   = blockIdx.x * 128;
    const int r    = lane >> 2;         // group id 0..7
    const int cq   = lane & 3;          // thread-in-group 0..3

    float acc[4][4][4];
#pragma unroll
    for (int i = 0; i < 4; i++)
#pragma unroll
        for (int j = 0; j < 4; j++)
#pragma unroll
            for (int t = 0; t < 4; t++) acc[i][j][t] = 0.0f;

    const int nkt = K >> 5;   // K/32
    float4 sa[4], sb[4];

    // ---- initial gmem prefetch (tile 0) ----
    {
#pragma unroll
        for (int it = 0; it < 4; it++) {
            int idx = it * 256 + tid;            // 1024 float4 = 128x32
            int row = idx >> 3, q = idx & 7;
            sa[it] = *(const float4*)&A[(size_t)(m0 + row) * lda + q * 4];
        }
        if (TRANS_B) {
#pragma unroll
            for (int it = 0; it < 4; it++) {
                int idx = it * 256 + tid;
                int row = idx >> 3, q = idx & 7;
                sb[it] = *(const float4*)&B[(size_t)(n0 + row) * ldb + q * 4];
            }
        } else {
#pragma unroll
            for (int it = 0; it < 4; it++) {
                int idx = it * 256 + tid;        // 32 k-rows x 32 quads
                int kk = idx >> 5, q = idx & 31;
                sb[it] = *(const float4*)&B[(size_t)kk * ldb + n0 + q * 4];
            }
        }
    }

    for (int kt = 0; kt < nkt; kt++) {
        // ---- store staged tile to smem with RNA tf32 rounding ----
#pragma unroll
        for (int it = 0; it < 4; it++) {
            int idx = it * 256 + tid;
            int row = idx >> 3, q = idx & 7;
            uint32_t* p = &As[row * 36 + q * 4];
            p[0] = f2tf(sa[it].x); p[1] = f2tf(sa[it].y);
            p[2] = f2tf(sa[it].z); p[3] = f2tf(sa[it].w);
        }
        if (TRANS_B) {
#pragma unroll
            for (int it = 0; it < 4; it++) {
                int idx = it * 256 + tid;
                int row = idx >> 3, q = idx & 7;
                uint32_t* p = &Bs[row * 36 + q * 4];
                p[0] = f2tf(sb[it].x); p[1] = f2tf(sb[it].y);
                p[2] = f2tf(sb[it].z); p[3] = f2tf(sb[it].w);
            }
        } else {
#pragma unroll
            for (int it = 0; it < 4; it++) {
                int idx = it * 256 + tid;
                int kk = idx >> 5, q = idx & 31;
                uint32_t* p = &Bs[kk * 136 + q * 4];
                p[0] = f2tf(sb[it].x); p[1] = f2tf(sb[it].y);
                p[2] = f2tf(sb[it].z); p[3] = f2tf(sb[it].w);
            }
        }
        __syncthreads();

        // ---- prefetch next tile while computing current ----
        if (kt + 1 < nkt) {
            int k0 = (kt + 1) * 32;
#pragma unroll
            for (int it = 0; it < 4; it++) {
                int idx = it * 256 + tid;
                int row = idx >> 3, q = idx & 7;
                sa[it] = *(const float4*)&A[(size_t)(m0 + row) * lda + k0 + q * 4];
            }
            if (TRANS_B) {
#pragma unroll
                for (int it = 0; it < 4; it++) {
                    int idx = it * 256 + tid;
                    int row = idx >> 3, q = idx & 7;
                    sb[it] = *(const float4*)&B[(size_t)(n0 + row) * ldb + k0 + q * 4];
                }
            } else {
#pragma unroll
                for (int it = 0; it < 4; it++) {
                    int idx = it * 256 + tid;
                    int kk = idx >> 5, q = idx & 31;
                    sb[it] = *(const float4*)&B[(size_t)(k0 + kk) * ldb + n0 + q * 4];
                }
            }
        }

        // ---- compute: 4 k8-steps x 16 mma ----
#pragma unroll
        for (int kk = 0; kk < 32; kk += 8) {
            uint32_t af[4][4];
#pragma unroll
            for (int i = 0; i < 4; i++) {
                int base = (wm + 16 * i + r) * 36 + kk + cq;
                af[i][0] = As[base];
                af[i][1] = As[base + 8 * 36];
                af[i][2] = As[base + 4];
                af[i][3] = As[base + 8 * 36 + 4];
            }
            uint32_t bf[4][2];
#pragma unroll
            for (int j = 0; j < 4; j++) {
                if (TRANS_B) {
                    int base = (wn + 8 * j + r) * 36 + kk + cq;
                    bf[j][0] = Bs[base];
                    bf[j][1] = Bs[base + 4];
                } else {
                    int base = (kk + cq) * 136 + wn + 8 * j + r;
                    bf[j][0] = Bs[base];
                    bf[j][1] = Bs[base + 4 * 136];
                }
            }
#pragma unroll
            for (int i = 0; i < 4; i++)
#pragma unroll
                for (int j = 0; j < 4; j++)
                    mma_tf32(acc[i][j], af[i], bf[j]);
        }
        __syncthreads();
    }

    // ---- epilogue: direct float2 stores ----
#pragma unroll
    for (int i = 0; i < 4; i++) {
#pragma unroll
        for (int j = 0; j < 4; j++) {
            int row = m0 + wm + 16 * i + r;
            int col = n0 + wn + 8 * j + 2 * cq;
            *(float2*)&C[(size_t)row * ldc + col] =
                make_float2(acc[i][j][0], acc[i][j][1]);
            *(float2*)&C[(size_t)(row + 8) * ldc + col] =
                make_float2(acc[i][j][2], acc[i][j][3]);
        }
    }
}

// ---------------------------------------------------------------------------
// RoPE: in-place on Q and K in [B,S,D] layout. Pure fp32 path (exp2f +
// sincosf): matches the fp32 reference trig to well under tolerance and
// avoids the fp64 pipe (prev version was fp64-latency-bound at 194us).
// ---------------------------------------------------------------------------
__global__ __launch_bounds__(256)
void rope_kernel(float* __restrict__ Q, float* __restrict__ K)
{
    int idx = blockIdx.x * blockDim.x + threadIdx.x;   // B*S*H*64 = 2^22
    int i = idx & 63;
    int h = (idx >> 6) & 15;
    int s = (idx >> 10) & (S_LEN - 1);
    int b = idx >> 21;

    // inv_freq = 10000^{-i/64} = 2^{-i * log2(10000)/64}
    float invf = exp2f(-0.20762050593046937f * (float)i);
    float ang = (float)s * invf;
    float sn, cs;
    sincosf(ang, &sn, &cs);

    size_t base = ((size_t)(b * S_LEN + s)) * D_MODEL + h * DH + i;
    float q1 = Q[base], q2 = Q[base + 64];
    Q[base]      = q1 * cs - q2 * sn;
    Q[base + 64] = q2 * cs + q1 * sn;
    float k1 = K[base], k2 = K[base + 64];
    K[base]      = k1 * cs - k2 * sn;
    K[base + 64] = k2 * cs + k1 * sn;
}

// ---------------------------------------------------------------------------
// Flash attention (causal), fp32. One block per (q-tile, b*h).
// BM=BN=64, dh=128, 256 threads. (unchanged from R1)
// ---------------------------------------------------------------------------
#define ATTN_SMEM_FLOATS (64*128 + 64*132 + 64*128 + 64*68)

__global__ __launch_bounds__(256)
void attn_kernel(const float* __restrict__ Q, const float* __restrict__ K,
                 const float* __restrict__ V, float* __restrict__ AO)
{
    extern __shared__ float sm[];
    float* Qs = sm;                  // 64*128
    float* Ks = Qs + 64 * 128;       // 64*132
    float* Vs = Ks + 64 * 132;       // 64*128
    float* Ps = Vs + 64 * 128;       // 64*68
    __shared__ float m_s[64], l_s[64], a_s[64];

    const int tid = threadIdx.x;
    const int tx = tid & 15;
    const int ty = tid >> 4;
    const int qt = blockIdx.x;                // 0..31
    const int bh = blockIdx.y;                // 0..31
    const int b = bh >> 4, h = bh & 15;
    const int q0 = qt * 64;
    const size_t head_off = (size_t)b * S_LEN * D_MODEL + (size_t)h * DH;
    const float scale = 0.08838834764831845f; // 1/sqrt(128)

#pragma unroll
    for (int it = 0; it < 8; it++) {
        int idx = it * 256 + tid;             // 2048 float4
        int r = idx >> 5, dq = idx & 31;
        float4 v = *(const float4*)&Q[head_off + (size_t)(q0 + r) * D_MODEL + dq * 4];
        *(float4*)&Qs[r * 128 + dq * 4] = v;
    }
    if (tid < 64) { m_s[tid] = -1e30f; l_s[tid] = 0.0f; }

    float o[4][8];
#pragma unroll
    for (int i = 0; i < 4; i++)
#pragma unroll
        for (int j = 0; j < 8; j++) o[i][j] = 0.0f;

    for (int kt = 0; kt <= qt; kt++) {
        const int k0 = kt * 64;
        __syncthreads();

#pragma unroll
        for (int it = 0; it < 8; it++) {
            int idx = it * 256 + tid;
            int c = idx >> 5, dq = idx & 31;
            float4 kv = *(const float4*)&K[head_off + (size_t)(k0 + c) * D_MODEL + dq * 4];
            *(float4*)&Ks[c * 132 + dq * 4] = kv;
            float4 vv = *(const float4*)&V[head_off + (size_t)(k0 + c) * D_MODEL + dq * 4];
            *(float4*)&Vs[c * 128 + dq * 4] = vv;
        }
        __syncthreads();

        float sacc[4][4];
#pragma unroll
        for (int i = 0; i < 4; i++)
#pragma unroll
            for (int j = 0; j < 4; j++) sacc[i][j] = 0.0f;

#pragma unroll 4
        for (int d = 0; d < 128; d += 4) {
            float4 kv[4];
#pragma unroll
            for (int j = 0; j < 4; j++)
                kv[j] = *(float4*)&Ks[(tx + 16 * j) * 132 + d];
#pragma unroll
            for (int i = 0; i < 4; i++) {
                float4 qv = *(float4*)&Qs[(ty + 16 * i) * 128 + d];
#pragma unroll
                for (int j = 0; j < 4; j++)
                    sacc[i][j] += qv.x * kv[j].x + qv.y * kv[j].y +
                                  qv.z * kv[j].z + qv.w * kv[j].w;
            }
        }

#pragma unroll
        for (int i = 0; i < 4; i++) {
            int r = ty + 16 * i, gq = q0 + r;
#pragma unroll
            for (int j = 0; j < 4; j++) {
                int c = tx + 16 * j;
                float v = sacc[i][j] * scale;
                if (k0 + c > gq) v = -1e30f;
                Ps[r * 68 + c] = v;
            }
        }
        __syncthreads();

        {
            int r = tid >> 2;
            int seg = (tid & 3) * 16;
            float4 vv[4];
            float mx = -1e30f;
#pragma unroll
            for (int k = 0; k < 4; k++) {
                vv[k] = *(float4*)&Ps[r * 68 + seg + k * 4];
                mx = fmaxf(mx, fmaxf(fmaxf(vv[k].x, vv[k].y), fmaxf(vv[k].z, vv[k].w)));
            }
            mx = fmaxf(mx, __shfl_xor_sync(0xffffffffu, mx, 1));
            mx = fmaxf(mx, __shfl_xor_sync(0xffffffffu, mx, 2));
            float m_old = m_s[r];
            float m_new = fmaxf(m_old, mx);
            float sum = 0.0f;
#pragma unroll
            for (int k = 0; k < 4; k++) {
                vv[k].x = __expf(vv[k].x - m_new);
                vv[k].y = __expf(vv[k].y - m_new);
                vv[k].z = __expf(vv[k].z - m_new);
                vv[k].w = __expf(vv[k].w - m_new);
                sum += vv[k].x + vv[k].y + vv[k].z + vv[k].w;
                *(float4*)&Ps[r * 68 + seg + k * 4] = vv[k];
            }
            sum += __shfl_xor_sync(0xffffffffu, sum, 1);
            sum += __shfl_xor_sync(0xffffffffu, sum, 2);
            if ((tid & 3) == 0) {
                float a = __expf(m_old - m_new);
                a_s[r] = a;
                m_s[r] = m_new;
                l_s[r] = l_s[r] * a + sum;
            }
        }
        __syncthreads();

        float al[4];
#pragma unroll
        for (int i = 0; i < 4; i++) al[i] = a_s[ty + 16 * i];
#pragma unroll
        for (int i = 0; i < 4; i++)
#pragma unroll
            for (int j = 0; j < 8; j++) o[i][j] *= al[i];

#pragma unroll 2
        for (int kk = 0; kk < 64; kk += 4) {
            float4 pv[4];
#pragma unroll
            for (int i = 0; i < 4; i++)
                pv[i] = *(float4*)&Ps[(ty + 16 * i) * 68 + kk];
#pragma unroll
            for (int u = 0; u < 4; u++) {
                float4 v0 = *(float4*)&Vs[(kk + u) * 128 + tx * 4];
                float4 v1 = *(float4*)&Vs[(kk + u) * 128 + 64 + tx * 4];
#pragma unroll
                for (int i = 0; i < 4; i++) {
                    float p = (u == 0) ? pv[i].x : (u == 1) ? pv[i].y
                             : (u == 2) ? pv[i].z : pv[i].w;
                    o[i][0] += p * v0.x; o[i][1] += p * v0.y;
                    o[i][2] += p * v0.z; o[i][3] += p * v0.w;
                    o[i][4] += p * v1.x; o[i][5] += p * v1.y;
                    o[i][6] += p * v1.z; o[i][7] += p * v1.w;
                }
            }
        }
    }

#pragma unroll
    for (int i = 0; i < 4; i++) {
        int r = ty + 16 * i;
        float inv = 1.0f / l_s[r];
        size_t rowp = head_off + (size_t)(q0 + r) * D_MODEL;
        float4 w0 = make_float4(o[i][0] * inv, o[i][1] * inv, o[i][2] * inv, o[i][3] * inv);
        float4 w1 = make_float4(o[i][4] * inv, o[i][5] * inv, o[i][6] * inv, o[i][7] * inv);
        *(float4*)&AO[rowp + tx * 4] = w0;
        *(float4*)&AO[rowp + 64 + tx * 4] = w1;
    }
}

// ---------------------------------------------------------------------------
extern "C" void kernel_launch(void* const* d_in, const int* in_sizes, int n_in,
                              void* d_out, int out_size)
{
    const float* x   = (const float*)d_in[0];
    const float* wq  = (const float*)d_in[1];
    const float* wkv = (const float*)d_in[2];
    const float* wo  = (const float*)d_in[3];
    float* out = (float*)d_out;

    float *Q, *K, *V, *AO;
    cudaGetSymbolAddress((void**)&Q,  g_Q);
    cudaGetSymbolAddress((void**)&K,  g_K);
    cudaGetSymbolAddress((void**)&V,  g_V);
    cudaGetSymbolAddress((void**)&AO, g_AO);

    dim3 blk(256);
    dim3 grd(D_MODEL / 128, M_TOT / 128);

    // Q = x @ wq^T   (NT, tf32 tensor cores)
    tf32_gemm<true><<<grd, blk>>>(x, wq, Q, M_TOT, D_MODEL, D_MODEL,
                                  D_MODEL, D_MODEL, D_MODEL);
    // K = x @ wkv[:, :2048]   (NN, ldb = 4096)
    tf32_gemm<false><<<grd, blk>>>(x, wkv, K, M_TOT, D_MODEL, D_MODEL,
                                   D_MODEL, 2 * D_MODEL, D_MODEL);
    // V = x @ wkv[:, 2048:]
    tf32_gemm<false><<<grd, blk>>>(x, wkv + D_MODEL, V, M_TOT, D_MODEL, D_MODEL,
                                   D_MODEL, 2 * D_MODEL, D_MODEL);

    // RoPE in place on Q, K
    rope_kernel<<<(BATCH * S_LEN * NUM_HEADS * 64) / 256, blk>>>(Q, K);

    // Flash attention
    static const int attn_smem = ATTN_SMEM_FLOATS * (int)sizeof(float);
    cudaFuncSetAttribute(attn_kernel, cudaFuncAttributeMaxDynamicSharedMemorySize,
                         attn_smem);
    attn_kernel<<<dim3(S_LEN / 64, BATCH * NUM_HEADS), blk, attn_smem>>>(Q, K, V, AO);

    // out = AO @ wo^T  (NT, tf32)
    tf32_gemm<true><<<grd, blk>>>(AO, wo, out, M_TOT, D_MODEL, D_MODEL,
                                  D_MODEL, D_MODEL, D_MODEL);
}

// round 3
// speedup vs baseline: 2.8557x; 1.4080x over previous
#include <cuda_runtime.h>
#include <math.h>
#include <stdint.h>

#define S_LEN 2048
#define D_MODEL 2048
#define NUM_HEADS 16
#define DH 128
#define BATCH 2
#define M_TOT (BATCH * S_LEN)   // 4096

// Scratch (allocation-free rule: __device__ globals)
__device__ float g_Q[(size_t)M_TOT * D_MODEL];
__device__ float g_K[(size_t)M_TOT * D_MODEL];
__device__ float g_V[(size_t)M_TOT * D_MODEL];
__device__ float g_AO[(size_t)M_TOT * D_MODEL];

// ---------------------------------------------------------------------------
// TF32 helpers
// ---------------------------------------------------------------------------
__device__ __forceinline__ uint32_t f2tf(float x) {
    uint32_t u;
    asm("cvt.rna.tf32.f32 %0, %1;" : "=r"(u) : "f"(x));
    return u;
}

__device__ __forceinline__ void mma_tf32(float* c, const uint32_t* a, const uint32_t* b) {
    asm volatile(
        "mma.sync.aligned.m16n8k8.row.col.f32.tf32.tf32.f32 "
        "{%0,%1,%2,%3}, {%4,%5,%6,%7}, {%8,%9}, {%0,%1,%2,%3};"
        : "+f"(c[0]), "+f"(c[1]), "+f"(c[2]), "+f"(c[3])
        : "r"(a[0]), "r"(a[1]), "r"(a[2]), "r"(a[3]), "r"(b[0]), "r"(b[1]));
}

// ---------------------------------------------------------------------------
// TF32 tensor-core GEMM (unchanged from R2): C[M,N] = A[M,K] * op(B)
// ---------------------------------------------------------------------------
template <bool TRANS_B>
__global__ __launch_bounds__(256)
void tf32_gemm(const float* __restrict__ A, const float* __restrict__ B,
               float* __restrict__ C, int M, int N, int K,
               int lda, int ldb, int ldc)
{
    __shared__ uint32_t As[128 * 36];
    __shared__ uint32_t Bs[TRANS_B ? (128 * 36) : (32 * 136)];

    const int tid  = threadIdx.x;
    const int lane = tid & 31;
    const int wid  = tid >> 5;
    const int wm   = (wid >> 2) * 64;
    const int wn   = (wid & 3) * 32;
    const int m0   = blockIdx.y * 128;
    const int n0   = blockIdx.x * 128;
    const int r    = lane >> 2;
    const int cq   = lane & 3;

    float acc[4][4][4];
#pragma unroll
    for (int i = 0; i < 4; i++)
#pragma unroll
        for (int j = 0; j < 4; j++)
#pragma unroll
            for (int t = 0; t < 4; t++) acc[i][j][t] = 0.0f;

    const int nkt = K >> 5;
    float4 sa[4], sb[4];

    {
#pragma unroll
        for (int it = 0; it < 4; it++) {
            int idx = it * 256 + tid;
            int row = idx >> 3, q = idx & 7;
            sa[it] = *(const float4*)&A[(size_t)(m0 + row) * lda + q * 4];
        }
        if (TRANS_B) {
#pragma unroll
            for (int it = 0; it < 4; it++) {
                int idx = it * 256 + tid;
                int row = idx >> 3, q = idx & 7;
                sb[it] = *(const float4*)&B[(size_t)(n0 + row) * ldb + q * 4];
            }
        } else {
#pragma unroll
            for (int it = 0; it < 4; it++) {
                int idx = it * 256 + tid;
                int kk = idx >> 5, q = idx & 31;
                sb[it] = *(const float4*)&B[(size_t)kk * ldb + n0 + q * 4];
            }
        }
    }

    for (int kt = 0; kt < nkt; kt++) {
#pragma unroll
        for (int it = 0; it < 4; it++) {
            int idx = it * 256 + tid;
            int row = idx >> 3, q = idx & 7;
            uint32_t* p = &As[row * 36 + q * 4];
            p[0] = f2tf(sa[it].x); p[1] = f2tf(sa[it].y);
            p[2] = f2tf(sa[it].z); p[3] = f2tf(sa[it].w);
        }
        if (TRANS_B) {
#pragma unroll
            for (int it = 0; it < 4; it++) {
                int idx = it * 256 + tid;
                int row = idx >> 3, q = idx & 7;
                uint32_t* p = &Bs[row * 36 + q * 4];
                p[0] = f2tf(sb[it].x); p[1] = f2tf(sb[it].y);
                p[2] = f2tf(sb[it].z); p[3] = f2tf(sb[it].w);
            }
        } else {
#pragma unroll
            for (int it = 0; it < 4; it++) {
                int idx = it * 256 + tid;
                int kk = idx >> 5, q = idx & 31;
                uint32_t* p = &Bs[kk * 136 + q * 4];
                p[0] = f2tf(sb[it].x); p[1] = f2tf(sb[it].y);
                p[2] = f2tf(sb[it].z); p[3] = f2tf(sb[it].w);
            }
        }
        __syncthreads();

        if (kt + 1 < nkt) {
            int k0 = (kt + 1) * 32;
#pragma unroll
            for (int it = 0; it < 4; it++) {
                int idx = it * 256 + tid;
                int row = idx >> 3, q = idx & 7;
                sa[it] = *(const float4*)&A[(size_t)(m0 + row) * lda + k0 + q * 4];
            }
            if (TRANS_B) {
#pragma unroll
                for (int it = 0; it < 4; it++) {
                    int idx = it * 256 + tid;
                    int row = idx >> 3, q = idx & 7;
                    sb[it] = *(const float4*)&B[(size_t)(n0 + row) * ldb + k0 + q * 4];
                }
            } else {
#pragma unroll
                for (int it = 0; it < 4; it++) {
                    int idx = it * 256 + tid;
                    int kk = idx >> 5, q = idx & 31;
                    sb[it] = *(const float4*)&B[(size_t)(k0 + kk) * ldb + n0 + q * 4];
                }
            }
        }

#pragma unroll
        for (int kk = 0; kk < 32; kk += 8) {
            uint32_t af[4][4];
#pragma unroll
            for (int i = 0; i < 4; i++) {
                int base = (wm + 16 * i + r) * 36 + kk + cq;
                af[i][0] = As[base];
                af[i][1] = As[base + 8 * 36];
                af[i][2] = As[base + 4];
                af[i][3] = As[base + 8 * 36 + 4];
            }
            uint32_t bf[4][2];
#pragma unroll
            for (int j = 0; j < 4; j++) {
                if (TRANS_B) {
                    int base = (wn + 8 * j + r) * 36 + kk + cq;
                    bf[j][0] = Bs[base];
                    bf[j][1] = Bs[base + 4];
                } else {
                    int base = (kk + cq) * 136 + wn + 8 * j + r;
                    bf[j][0] = Bs[base];
                    bf[j][1] = Bs[base + 4 * 136];
                }
            }
#pragma unroll
            for (int i = 0; i < 4; i++)
#pragma unroll
                for (int j = 0; j < 4; j++)
                    mma_tf32(acc[i][j], af[i], bf[j]);
        }
        __syncthreads();
    }

#pragma unroll
    for (int i = 0; i < 4; i++) {
#pragma unroll
        for (int j = 0; j < 4; j++) {
            int row = m0 + wm + 16 * i + r;
            int col = n0 + wn + 8 * j + 2 * cq;
            *(float2*)&C[(size_t)row * ldc + col] =
                make_float2(acc[i][j][0], acc[i][j][1]);
            *(float2*)&C[(size_t)(row + 8) * ldc + col] =
                make_float2(acc[i][j][2], acc[i][j][3]);
        }
    }
}

// ---------------------------------------------------------------------------
// RoPE (fp32 path, unchanged from R2)
// ---------------------------------------------------------------------------
__global__ __launch_bounds__(256)
void rope_kernel(float* __restrict__ Q, float* __restrict__ K)
{
    int idx = blockIdx.x * blockDim.x + threadIdx.x;
    int i = idx & 63;
    int h = (idx >> 6) & 15;
    int s = (idx >> 10) & (S_LEN - 1);
    int b = idx >> 21;

    float invf = exp2f(-0.20762050593046937f * (float)i);
    float ang = (float)s * invf;
    float sn, cs;
    sincosf(ang, &sn, &cs);

    size_t base = ((size_t)(b * S_LEN + s)) * D_MODEL + h * DH + i;
    float q1 = Q[base], q2 = Q[base + 64];
    Q[base]      = q1 * cs - q2 * sn;
    Q[base + 64] = q2 * cs + q1 * sn;
    float k1 = K[base], k2 = K[base + 64];
    K[base]      = k1 * cs - k2 * sn;
    K[base + 64] = k2 * cs + k1 * sn;
}

// ---------------------------------------------------------------------------
// TF32 flash attention (causal). One block per (q-tile 64, b*h), 256 thr.
// 8 warps as 4(m)x2(n). Warp S-tile 16x32, warp O-tile 16x64.
// Smem strides chosen so every mma fragment LDS is conflict-free:
//   Q/K stride 132: banks 4r+cq (A) / 4r+cq (B)  -> 32 distinct
//   V   stride 136: banks 8cq+r  (B, n-contiguous rows, no transpose needed)
//   P   stride 68 : banks 4r+cq  (A)
// Softmax in fp32; exp values written back as tf32 bit patterns for PV.
// ---------------------------------------------------------------------------
#define ATTN_SMEM_U32 (64*132 + 64*132 + 64*136 + 64*68)

__global__ __launch_bounds__(256)
void attn_kernel(const float* __restrict__ Q, const float* __restrict__ K,
                 const float* __restrict__ V, float* __restrict__ AO)
{
    extern __shared__ uint32_t sm[];
    uint32_t* Qs = sm;                 // 64*132 (tf32)
    uint32_t* Ks = Qs + 64 * 132;      // 64*132 (tf32)
    uint32_t* Vs = Ks + 64 * 132;      // 64*136 (tf32, [s_kv][dh])
    uint32_t* Pu = Vs + 64 * 136;      // 64*68  (fp32 then tf32)
    float*    Pf = (float*)Pu;
    __shared__ float m_s[64], l_s[64], a_s[64];

    const int tid  = threadIdx.x;
    const int lane = tid & 31;
    const int wid  = tid >> 5;
    const int r    = lane >> 2;        // 0..7
    const int cq   = lane & 3;         // 0..3
    const int wm   = (wid >> 1) * 16;  // warp m offset (rows)
    const int wns  = (wid & 1) * 32;   // warp n offset for S
    const int wno  = (wid & 1) * 64;   // warp n offset for O

    const int qt = (int)gridDim.x - 1 - (int)blockIdx.x;  // heavy blocks first
    const int bh = blockIdx.y;
    const int b = bh >> 4, h = bh & 15;
    const int q0 = qt * 64;
    const size_t head_off = (size_t)b * S_LEN * D_MODEL + (size_t)h * DH;
    const float scale = 0.08838834764831845f; // 1/sqrt(128)

    // Load Q tile -> tf32 smem
#pragma unroll
    for (int it = 0; it < 8; it++) {
        int idx = it * 256 + tid;             // 2048 float4
        int row = idx >> 5, dq = idx & 31;
        float4 v = *(const float4*)&Q[head_off + (size_t)(q0 + row) * D_MODEL + dq * 4];
        uint32_t* p = &Qs[row * 132 + dq * 4];
        p[0] = f2tf(v.x); p[1] = f2tf(v.y); p[2] = f2tf(v.z); p[3] = f2tf(v.w);
    }
    if (tid < 64) { m_s[tid] = -1e30f; l_s[tid] = 0.0f; }

    float o[8][4];   // 8 n-atoms x {c0,c1 (row r), c2,c3 (row r+8)}
#pragma unroll
    for (int j = 0; j < 8; j++)
#pragma unroll
        for (int t = 0; t < 4; t++) o[j][t] = 0.0f;

    for (int kt = 0; kt <= qt; kt++) {
        const int k0 = kt * 64;
        __syncthreads();   // prev PV (reads Ks? no: Pu,Vs) done before overwrite

        // Load K,V tiles -> tf32 smem
#pragma unroll
        for (int it = 0; it < 8; it++) {
            int idx = it * 256 + tid;
            int c = idx >> 5, dq = idx & 31;
            float4 kv = *(const float4*)&K[head_off + (size_t)(k0 + c) * D_MODEL + dq * 4];
            uint32_t* pk = &Ks[c * 132 + dq * 4];
            pk[0] = f2tf(kv.x); pk[1] = f2tf(kv.y); pk[2] = f2tf(kv.z); pk[3] = f2tf(kv.w);
            float4 vv = *(const float4*)&V[head_off + (size_t)(k0 + c) * D_MODEL + dq * 4];
            uint32_t* pv = &Vs[c * 136 + dq * 4];
            pv[0] = f2tf(vv.x); pv[1] = f2tf(vv.y); pv[2] = f2tf(vv.z); pv[3] = f2tf(vv.w);
        }
        __syncthreads();

        // --- S = Q K^T : warp tile 16x32, 16 k-steps x 4 n-atoms ---
        float sacc[4][4];
#pragma unroll
        for (int j = 0; j < 4; j++)
#pragma unroll
            for (int t = 0; t < 4; t++) sacc[j][t] = 0.0f;

#pragma unroll
        for (int kk = 0; kk < 128; kk += 8) {
            uint32_t af[4];
            int abase = (wm + r) * 132 + kk + cq;
            af[0] = Qs[abase];
            af[1] = Qs[abase + 8 * 132];
            af[2] = Qs[abase + 4];
            af[3] = Qs[abase + 8 * 132 + 4];
            uint32_t bf[4][2];
#pragma unroll
            for (int j = 0; j < 4; j++) {
                int bbase = (wns + 8 * j + r) * 132 + kk + cq;
                bf[j][0] = Ks[bbase];
                bf[j][1] = Ks[bbase + 4];
            }
#pragma unroll
            for (int j = 0; j < 4; j++)
                mma_tf32(sacc[j], af, bf[j]);
        }

        // Scale + causal mask -> Pf (fp32)
        if (kt == qt) {
#pragma unroll
            for (int j = 0; j < 4; j++) {
                int c0 = wns + 8 * j + 2 * cq;
#pragma unroll
                for (int t = 0; t < 4; t++) {
                    int row = wm + r + (t >> 1) * 8;
                    int col = c0 + (t & 1);
                    float v = sacc[j][t] * scale;
                    if (col > row) v = -1e30f;   // k0 == q0 on diagonal
                    Pf[row * 68 + col] = v;
                }
            }
        } else {
#pragma unroll
            for (int j = 0; j < 4; j++) {
                int c0 = wns + 8 * j + 2 * cq;
                Pf[(wm + r) * 68 + c0]     = sacc[j][0] * scale;
                Pf[(wm + r) * 68 + c0 + 1] = sacc[j][1] * scale;
                Pf[(wm + r + 8) * 68 + c0]     = sacc[j][2] * scale;
                Pf[(wm + r + 8) * 68 + c0 + 1] = sacc[j][3] * scale;
            }
        }
        __syncthreads();

        // --- Online softmax (fp32), write back exp as tf32 bits ---
        {
            int row = tid >> 2;
            int seg = (tid & 3) * 16;
            float4 vv[4];
            float mx = -1e30f;
#pragma unroll
            for (int k = 0; k < 4; k++) {
                vv[k] = *(float4*)&Pf[row * 68 + seg + k * 4];
                mx = fmaxf(mx, fmaxf(fmaxf(vv[k].x, vv[k].y), fmaxf(vv[k].z, vv[k].w)));
            }
            mx = fmaxf(mx, __shfl_xor_sync(0xffffffffu, mx, 1));
            mx = fmaxf(mx, __shfl_xor_sync(0xffffffffu, mx, 2));
            float m_old = m_s[row];
            float m_new = fmaxf(m_old, mx);
            float sum = 0.0f;
#pragma unroll
            for (int k = 0; k < 4; k++) {
                vv[k].x = __expf(vv[k].x - m_new);
                vv[k].y = __expf(vv[k].y - m_new);
                vv[k].z = __expf(vv[k].z - m_new);
                vv[k].w = __expf(vv[k].w - m_new);
                sum += vv[k].x + vv[k].y + vv[k].z + vv[k].w;
                uint32_t* p = &Pu[row * 68 + seg + k * 4];
                p[0] = f2tf(vv[k].x); p[1] = f2tf(vv[k].y);
                p[2] = f2tf(vv[k].z); p[3] = f2tf(vv[k].w);
            }
            sum += __shfl_xor_sync(0xffffffffu, sum, 1);
            sum += __shfl_xor_sync(0xffffffffu, sum, 2);
            if ((tid & 3) == 0) {
                float a = __expf(m_old - m_new);
                a_s[row] = a;
                m_s[row] = m_new;
                l_s[row] = l_s[row] * a + sum;
            }
        }
        __syncthreads();

        // --- Rescale O, then O += P @ V : warp tile 16x64 ---
        float a0 = a_s[wm + r], a1 = a_s[wm + r + 8];
#pragma unroll
        for (int j = 0; j < 8; j++) {
            o[j][0] *= a0; o[j][1] *= a0;
            o[j][2] *= a1; o[j][3] *= a1;
        }

#pragma unroll
        for (int kk = 0; kk < 64; kk += 8) {
            uint32_t af[4];
            int abase = (wm + r) * 68 + kk + cq;
            af[0] = Pu[abase];
            af[1] = Pu[abase + 8 * 68];
            af[2] = Pu[abase + 4];
            af[3] = Pu[abase + 8 * 68 + 4];
            uint32_t bf[8][2];
#pragma unroll
            for (int j = 0; j < 8; j++) {
                int bbase = (kk + cq) * 136 + wno + 8 * j + r;
                bf[j][0] = Vs[bbase];
                bf[j][1] = Vs[bbase + 4 * 136];
            }
#pragma unroll
            for (int j = 0; j < 8; j++)
                mma_tf32(o[j], af, bf[j]);
        }
    }

    // Epilogue: normalize and store
    {
        float inv0 = 1.0f / l_s[wm + r];
        float inv1 = 1.0f / l_s[wm + r + 8];
        size_t row0 = head_off + (size_t)(q0 + wm + r) * D_MODEL;
        size_t row1 = head_off + (size_t)(q0 + wm + r + 8) * D_MODEL;
#pragma unroll
        for (int j = 0; j < 8; j++) {
            int col = wno + 8 * j + 2 * cq;
            *(float2*)&AO[row0 + col] = make_float2(o[j][0] * inv0, o[j][1] * inv0);
            *(float2*)&AO[row1 + col] = make_float2(o[j][2] * inv1, o[j][3] * inv1);
        }
    }
}

// ---------------------------------------------------------------------------
extern "C" void kernel_launch(void* const* d_in, const int* in_sizes, int n_in,
                              void* d_out, int out_size)
{
    const float* x   = (const float*)d_in[0];
    const float* wq  = (const float*)d_in[1];
    const float* wkv = (const float*)d_in[2];
    const float* wo  = (const float*)d_in[3];
    float* out = (float*)d_out;

    float *Q, *K, *V, *AO;
    cudaGetSymbolAddress((void**)&Q,  g_Q);
    cudaGetSymbolAddress((void**)&K,  g_K);
    cudaGetSymbolAddress((void**)&V,  g_V);
    cudaGetSymbolAddress((void**)&AO, g_AO);

    dim3 blk(256);
    dim3 grd(D_MODEL / 128, M_TOT / 128);

    tf32_gemm<true><<<grd, blk>>>(x, wq, Q, M_TOT, D_MODEL, D_MODEL,
                                  D_MODEL, D_MODEL, D_MODEL);
    tf32_gemm<false><<<grd, blk>>>(x, wkv, K, M_TOT, D_MODEL, D_MODEL,
                                   D_MODEL, 2 * D_MODEL, D_MODEL);
    tf32_gemm<false><<<grd, blk>>>(x, wkv + D_MODEL, V, M_TOT, D_MODEL, D_MODEL,
                                   D_MODEL, 2 * D_MODEL, D_MODEL);

    rope_kernel<<<(BATCH * S_LEN * NUM_HEADS * 64) / 256, blk>>>(Q, K);

    static const int attn_smem = ATTN_SMEM_U32 * (int)sizeof(uint32_t);
    cudaFuncSetAttribute(attn_kernel, cudaFuncAttributeMaxDynamicSharedMemorySize,
                         attn_smem);
    attn_kernel<<<dim3(S_LEN / 64, BATCH * NUM_HEADS), blk, attn_smem>>>(Q, K, V, AO);

    tf32_gemm<true><<<grd, blk>>>(AO, wo, out, M_TOT, D_MODEL, D_MODEL,
                                  D_MODEL, D_MODEL, D_MODEL);
}

// round 4
// speedup vs baseline: 3.1135x; 1.0903x over previous
#include <cuda_runtime.h>
#include <math.h>
#include <stdint.h>

#define S_LEN 2048
#define D_MODEL 2048
#define NUM_HEADS 16
#define DH 128
#define BATCH 2
#define M_TOT (BATCH * S_LEN)   // 4096

// Scratch (allocation-free rule: __device__ globals)
__device__ float g_Q[(size_t)M_TOT * D_MODEL];
__device__ float g_K[(size_t)M_TOT * D_MODEL];
__device__ float g_V[(size_t)M_TOT * D_MODEL];
__device__ float g_AO[(size_t)M_TOT * D_MODEL];

// ---------------------------------------------------------------------------
// TF32 helpers
// ---------------------------------------------------------------------------
__device__ __forceinline__ uint32_t f2tf(float x) {
    uint32_t u;
    asm("cvt.rna.tf32.f32 %0, %1;" : "=r"(u) : "f"(x));
    return u;
}

__device__ __forceinline__ void mma_tf32(float* c, const uint32_t* a, const uint32_t* b) {
    asm volatile(
        "mma.sync.aligned.m16n8k8.row.col.f32.tf32.tf32.f32 "
        "{%0,%1,%2,%3}, {%4,%5,%6,%7}, {%8,%9}, {%0,%1,%2,%3};"
        : "+f"(c[0]), "+f"(c[1]), "+f"(c[2]), "+f"(c[3])
        : "r"(a[0]), "r"(a[1]), "r"(a[2]), "r"(a[3]), "r"(b[0]), "r"(b[1]));
}

// ---------------------------------------------------------------------------
// TF32 tensor-core GEMM (unchanged from R2): C[M,N] = A[M,K] * op(B)
// ---------------------------------------------------------------------------
template <bool TRANS_B>
__global__ __launch_bounds__(256)
void tf32_gemm(const float* __restrict__ A, const float* __restrict__ B,
               float* __restrict__ C, int M, int N, int K,
               int lda, int ldb, int ldc)
{
    __shared__ uint32_t As[128 * 36];
    __shared__ uint32_t Bs[TRANS_B ? (128 * 36) : (32 * 136)];

    const int tid  = threadIdx.x;
    const int lane = tid & 31;
    const int wid  = tid >> 5;
    const int wm   = (wid >> 2) * 64;
    const int wn   = (wid & 3) * 32;
    const int m0   = blockIdx.y * 128;
    const int n0   = blockIdx.x * 128;
    const int r    = lane >> 2;
    const int cq   = lane & 3;

    float acc[4][4][4];
#pragma unroll
    for (int i = 0; i < 4; i++)
#pragma unroll
        for (int j = 0; j < 4; j++)
#pragma unroll
            for (int t = 0; t < 4; t++) acc[i][j][t] = 0.0f;

    const int nkt = K >> 5;
    float4 sa[4], sb[4];

    {
#pragma unroll
        for (int it = 0; it < 4; it++) {
            int idx = it * 256 + tid;
            int row = idx >> 3, q = idx & 7;
            sa[it] = *(const float4*)&A[(size_t)(m0 + row) * lda + q * 4];
        }
        if (TRANS_B) {
#pragma unroll
            for (int it = 0; it < 4; it++) {
                int idx = it * 256 + tid;
                int row = idx >> 3, q = idx & 7;
                sb[it] = *(const float4*)&B[(size_t)(n0 + row) * ldb + q * 4];
            }
        } else {
#pragma unroll
            for (int it = 0; it < 4; it++) {
                int idx = it * 256 + tid;
                int kk = idx >> 5, q = idx & 31;
                sb[it] = *(const float4*)&B[(size_t)kk * ldb + n0 + q * 4];
            }
        }
    }

    for (int kt = 0; kt < nkt; kt++) {
#pragma unroll
        for (int it = 0; it < 4; it++) {
            int idx = it * 256 + tid;
            int row = idx >> 3, q = idx & 7;
            uint32_t* p = &As[row * 36 + q * 4];
            p[0] = f2tf(sa[it].x); p[1] = f2tf(sa[it].y);
            p[2] = f2tf(sa[it].z); p[3] = f2tf(sa[it].w);
        }
        if (TRANS_B) {
#pragma unroll
            for (int it = 0; it < 4; it++) {
                int idx = it * 256 + tid;
                int row = idx >> 3, q = idx & 7;
                uint32_t* p = &Bs[row * 36 + q * 4];
                p[0] = f2tf(sb[it].x); p[1] = f2tf(sb[it].y);
                p[2] = f2tf(sb[it].z); p[3] = f2tf(sb[it].w);
            }
        } else {
#pragma unroll
            for (int it = 0; it < 4; it++) {
                int idx = it * 256 + tid;
                int kk = idx >> 5, q = idx & 31;
                uint32_t* p = &Bs[kk * 136 + q * 4];
                p[0] = f2tf(sb[it].x); p[1] = f2tf(sb[it].y);
                p[2] = f2tf(sb[it].z); p[3] = f2tf(sb[it].w);
            }
        }
        __syncthreads();

        if (kt + 1 < nkt) {
            int k0 = (kt + 1) * 32;
#pragma unroll
            for (int it = 0; it < 4; it++) {
                int idx = it * 256 + tid;
                int row = idx >> 3, q = idx & 7;
                sa[it] = *(const float4*)&A[(size_t)(m0 + row) * lda + k0 + q * 4];
            }
            if (TRANS_B) {
#pragma unroll
                for (int it = 0; it < 4; it++) {
                    int idx = it * 256 + tid;
                    int row = idx >> 3, q = idx & 7;
                    sb[it] = *(const float4*)&B[(size_t)(n0 + row) * ldb + k0 + q * 4];
                }
            } else {
#pragma unroll
                for (int it = 0; it < 4; it++) {
                    int idx = it * 256 + tid;
                    int kk = idx >> 5, q = idx & 31;
                    sb[it] = *(const float4*)&B[(size_t)(k0 + kk) * ldb + n0 + q * 4];
                }
            }
        }

#pragma unroll
        for (int kk = 0; kk < 32; kk += 8) {
            uint32_t af[4][4];
#pragma unroll
            for (int i = 0; i < 4; i++) {
                int base = (wm + 16 * i + r) * 36 + kk + cq;
                af[i][0] = As[base];
                af[i][1] = As[base + 8 * 36];
                af[i][2] = As[base + 4];
                af[i][3] = As[base + 8 * 36 + 4];
            }
            uint32_t bf[4][2];
#pragma unroll
            for (int j = 0; j < 4; j++) {
                if (TRANS_B) {
                    int base = (wn + 8 * j + r) * 36 + kk + cq;
                    bf[j][0] = Bs[base];
                    bf[j][1] = Bs[base + 4];
                } else {
                    int base = (kk + cq) * 136 + wn + 8 * j + r;
                    bf[j][0] = Bs[base];
                    bf[j][1] = Bs[base + 4 * 136];
                }
            }
#pragma unroll
            for (int i = 0; i < 4; i++)
#pragma unroll
                for (int j = 0; j < 4; j++)
                    mma_tf32(acc[i][j], af[i], bf[j]);
        }
        __syncthreads();
    }

#pragma unroll
    for (int i = 0; i < 4; i++) {
#pragma unroll
        for (int j = 0; j < 4; j++) {
            int row = m0 + wm + 16 * i + r;
            int col = n0 + wn + 8 * j + 2 * cq;
            *(float2*)&C[(size_t)row * ldc + col] =
                make_float2(acc[i][j][0], acc[i][j][1]);
            *(float2*)&C[(size_t)(row + 8) * ldc + col] =
                make_float2(acc[i][j][2], acc[i][j][3]);
        }
    }
}

// ---------------------------------------------------------------------------
// RoPE (fp32 path, unchanged)
// ---------------------------------------------------------------------------
__global__ __launch_bounds__(256)
void rope_kernel(float* __restrict__ Q, float* __restrict__ K)
{
    int idx = blockIdx.x * blockDim.x + threadIdx.x;
    int i = idx & 63;
    int h = (idx >> 6) & 15;
    int s = (idx >> 10) & (S_LEN - 1);
    int b = idx >> 21;

    float invf = exp2f(-0.20762050593046937f * (float)i);
    float ang = (float)s * invf;
    float sn, cs;
    sincosf(ang, &sn, &cs);

    size_t base = ((size_t)(b * S_LEN + s)) * D_MODEL + h * DH + i;
    float q1 = Q[base], q2 = Q[base + 64];
    Q[base]      = q1 * cs - q2 * sn;
    Q[base + 64] = q2 * cs + q1 * sn;
    float k1 = K[base], k2 = K[base + 64];
    K[base]      = k1 * cs - k2 * sn;
    K[base + 64] = k2 * cs + k1 * sn;
}

// ---------------------------------------------------------------------------
// TF32 flash attention v2 (causal). Q-tile 128 x kv-tile 64, 256 threads.
// 8 warps; warp w owns rows [16w, 16w+16) across ALL 64 kv cols:
//   -> softmax state (m, l) entirely in registers, row-reduce = 2 shfls
//   -> P handoff via per-warp smem stripe + __syncwarp only
//   -> 2 block syncs per kv tile (K/V buffer protect + availability)
// Warps fully below the diagonal skip S/softmax/PV.
// Bank-conflict-free fragment addressing:
//   Q/K stride 132 (banks 4r+cq), V stride 136 (banks 8cq+r), P stride 68.
// ---------------------------------------------------------------------------
#define ATTN_SMEM_U32 (128*132 + 64*132 + 64*136 + 8*16*68)

__global__ __launch_bounds__(256, 1)
void attn_kernel(const float* __restrict__ Q, const float* __restrict__ K,
                 const float* __restrict__ V, float* __restrict__ AO)
{
    extern __shared__ uint32_t sm[];
    uint32_t* Qs = sm;                   // 128*132 (tf32)
    uint32_t* Ks = Qs + 128 * 132;       // 64*132
    uint32_t* Vs = Ks + 64 * 132;        // 64*136  [kv_row][dh]
    uint32_t* Ps = Vs + 64 * 136;        // 8 warps x 16*68

    const int tid  = threadIdx.x;
    const int lane = tid & 31;
    const int wid  = tid >> 5;
    const int r    = lane >> 2;          // 0..7
    const int cq   = lane & 3;           // 0..3
    const int wm   = wid * 16;           // warp's row offset in q-tile
    uint32_t* Pw   = Ps + wid * (16 * 68);

    const int qt = (int)gridDim.x - 1 - (int)blockIdx.x;  // heavy first
    const int bh = blockIdx.y;
    const int b = bh >> 4, h = bh & 15;
    const int q0 = qt * 128;
    const size_t head_off = (size_t)b * S_LEN * D_MODEL + (size_t)h * DH;
    const float scale = 0.08838834764831845f; // 1/sqrt(128)

    // Load Q tile (128 rows x 128) -> tf32 smem
#pragma unroll
    for (int it = 0; it < 16; it++) {
        int idx = it * 256 + tid;            // 4096 float4
        int row = idx >> 5, dq = idx & 31;
        float4 v = *(const float4*)&Q[head_off + (size_t)(q0 + row) * D_MODEL + dq * 4];
        uint32_t* p = &Qs[row * 132 + dq * 4];
        p[0] = f2tf(v.x); p[1] = f2tf(v.y); p[2] = f2tf(v.z); p[3] = f2tf(v.w);
    }

    float o[16][4];                      // 16 n-atoms x {r:c0,c1 ; r+8:c2,c3}
#pragma unroll
    for (int j = 0; j < 16; j++)
#pragma unroll
        for (int t = 0; t < 4; t++) o[j][t] = 0.0f;
    float m0 = -1e30f, m1 = -1e30f, l0 = 0.0f, l1 = 0.0f;

    const int nkt = 2 * qt + 2;
    for (int kt = 0; kt < nkt; kt++) {
        const int k0 = kt * 64;
        __syncthreads();   // previous iteration done with Ks/Vs

        // Load K,V tiles (64 rows x 128) -> tf32 smem
#pragma unroll
        for (int it = 0; it < 8; it++) {
            int idx = it * 256 + tid;
            int c = idx >> 5, dq = idx & 31;
            float4 kv = *(const float4*)&K[head_off + (size_t)(k0 + c) * D_MODEL + dq * 4];
            uint32_t* pk = &Ks[c * 132 + dq * 4];
            pk[0] = f2tf(kv.x); pk[1] = f2tf(kv.y); pk[2] = f2tf(kv.z); pk[3] = f2tf(kv.w);
            float4 vv = *(const float4*)&V[head_off + (size_t)(k0 + c) * D_MODEL + dq * 4];
            uint32_t* pv = &Vs[c * 136 + dq * 4];
            pv[0] = f2tf(vv.x); pv[1] = f2tf(vv.y); pv[2] = f2tf(vv.z); pv[3] = f2tf(vv.w);
        }
        __syncthreads();

        // Warp fully below diagonal? (all cols masked) -> skip
        if (k0 > q0 + wm + 15) continue;

        // --- S stripe = Q[wm..wm+16) K^T : 16 k-steps x 8 n-atoms ---
        float sacc[8][4];
#pragma unroll
        for (int j = 0; j < 8; j++)
#pragma unroll
            for (int t = 0; t < 4; t++) sacc[j][t] = 0.0f;

#pragma unroll
        for (int kk = 0; kk < 128; kk += 8) {
            uint32_t af[4];
            int abase = (wm + r) * 132 + kk + cq;
            af[0] = Qs[abase];
            af[1] = Qs[abase + 8 * 132];
            af[2] = Qs[abase + 4];
            af[3] = Qs[abase + 8 * 132 + 4];
            uint32_t bf[8][2];
#pragma unroll
            for (int j = 0; j < 8; j++) {
                int bbase = (8 * j + r) * 132 + kk + cq;
                bf[j][0] = Ks[bbase];
                bf[j][1] = Ks[bbase + 4];
            }
#pragma unroll
            for (int j = 0; j < 8; j++)
                mma_tf32(sacc[j], af, bf[j]);
        }

        // --- scale + causal mask (only needed near the diagonal) ---
        const int row0 = q0 + wm + r;        // global q row (t0,t1)
        const int row1 = row0 + 8;           // (t2,t3)
        if (k0 + 63 > q0 + wm) {
#pragma unroll
            for (int j = 0; j < 8; j++) {
                int c0 = k0 + 8 * j + 2 * cq;
                sacc[j][0] = (c0     > row0) ? -1e30f : sacc[j][0] * scale;
                sacc[j][1] = (c0 + 1 > row0) ? -1e30f : sacc[j][1] * scale;
                sacc[j][2] = (c0     > row1) ? -1e30f : sacc[j][2] * scale;
                sacc[j][3] = (c0 + 1 > row1) ? -1e30f : sacc[j][3] * scale;
            }
        } else {
#pragma unroll
            for (int j = 0; j < 8; j++)
#pragma unroll
                for (int t = 0; t < 4; t++) sacc[j][t] *= scale;
        }

        // --- register softmax: row reduce within quad (lanes share r) ---
        float mx0 = -1e30f, mx1 = -1e30f;
#pragma unroll
        for (int j = 0; j < 8; j++) {
            mx0 = fmaxf(mx0, fmaxf(sacc[j][0], sacc[j][1]));
            mx1 = fmaxf(mx1, fmaxf(sacc[j][2], sacc[j][3]));
        }
        mx0 = fmaxf(mx0, __shfl_xor_sync(0xffffffffu, mx0, 1));
        mx0 = fmaxf(mx0, __shfl_xor_sync(0xffffffffu, mx0, 2));
        mx1 = fmaxf(mx1, __shfl_xor_sync(0xffffffffu, mx1, 1));
        mx1 = fmaxf(mx1, __shfl_xor_sync(0xffffffffu, mx1, 2));
        float mn0 = fmaxf(m0, mx0);
        float mn1 = fmaxf(m1, mx1);

        float sum0 = 0.0f, sum1 = 0.0f;
#pragma unroll
        for (int j = 0; j < 8; j++) {
            float p0 = __expf(sacc[j][0] - mn0);
            float p1 = __expf(sacc[j][1] - mn0);
            float p2 = __expf(sacc[j][2] - mn1);
            float p3 = __expf(sacc[j][3] - mn1);
            sum0 += p0 + p1;
            sum1 += p2 + p3;
            int c = 8 * j + 2 * cq;
            Pw[r * 68 + c]           = f2tf(p0);
            Pw[r * 68 + c + 1]       = f2tf(p1);
            Pw[(r + 8) * 68 + c]     = f2tf(p2);
            Pw[(r + 8) * 68 + c + 1] = f2tf(p3);
        }
        sum0 += __shfl_xor_sync(0xffffffffu, sum0, 1);
        sum0 += __shfl_xor_sync(0xffffffffu, sum0, 2);
        sum1 += __shfl_xor_sync(0xffffffffu, sum1, 1);
        sum1 += __shfl_xor_sync(0xffffffffu, sum1, 2);

        float a0 = __expf(m0 - mn0);
        float a1 = __expf(m1 - mn1);
        m0 = mn0; m1 = mn1;
        l0 = l0 * a0 + sum0;
        l1 = l1 * a1 + sum1;
#pragma unroll
        for (int j = 0; j < 16; j++) {
            o[j][0] *= a0; o[j][1] *= a0;
            o[j][2] *= a1; o[j][3] *= a1;
        }

        __syncwarp();   // P stripe visible to all lanes of this warp

        // --- O += P @ V : 8 k-steps x 16 n-atoms ---
#pragma unroll
        for (int kk = 0; kk < 64; kk += 8) {
            uint32_t af[4];
            int abase = r * 68 + kk + cq;
            af[0] = Pw[abase];
            af[1] = Pw[abase + 8 * 68];
            af[2] = Pw[abase + 4];
            af[3] = Pw[abase + 8 * 68 + 4];
#pragma unroll
            for (int j = 0; j < 16; j++) {
                uint32_t bf[2];
                int bbase = (kk + cq) * 136 + 8 * j + r;
                bf[0] = Vs[bbase];
                bf[1] = Vs[bbase + 4 * 136];
                mma_tf32(o[j], af, bf);
            }
        }
    }

    // Epilogue: normalize and store
    {
        float inv0 = 1.0f / l0;
        float inv1 = 1.0f / l1;
        size_t rp0 = head_off + (size_t)(q0 + wm + r) * D_MODEL;
        size_t rp1 = head_off + (size_t)(q0 + wm + r + 8) * D_MODEL;
#pragma unroll
        for (int j = 0; j < 16; j++) {
            int col = 8 * j + 2 * cq;
            *(float2*)&AO[rp0 + col] = make_float2(o[j][0] * inv0, o[j][1] * inv0);
            *(float2*)&AO[rp1 + col] = make_float2(o[j][2] * inv1, o[j][3] * inv1);
        }
    }
}

// ---------------------------------------------------------------------------
extern "C" void kernel_launch(void* const* d_in, const int* in_sizes, int n_in,
                              void* d_out, int out_size)
{
    const float* x   = (const float*)d_in[0];
    const float* wq  = (const float*)d_in[1];
    const float* wkv = (const float*)d_in[2];
    const float* wo  = (const float*)d_in[3];
    float* out = (float*)d_out;

    float *Q, *K, *V, *AO;
    cudaGetSymbolAddress((void**)&Q,  g_Q);
    cudaGetSymbolAddress((void**)&K,  g_K);
    cudaGetSymbolAddress((void**)&V,  g_V);
    cudaGetSymbolAddress((void**)&AO, g_AO);

    dim3 blk(256);
    dim3 grd(D_MODEL / 128, M_TOT / 128);

    tf32_gemm<true><<<grd, blk>>>(x, wq, Q, M_TOT, D_MODEL, D_MODEL,
                                  D_MODEL, D_MODEL, D_MODEL);
    tf32_gemm<false><<<grd, blk>>>(x, wkv, K, M_TOT, D_MODEL, D_MODEL,
                                   D_MODEL, 2 * D_MODEL, D_MODEL);
    tf32_gemm<false><<<grd, blk>>>(x, wkv + D_MODEL, V, M_TOT, D_MODEL, D_MODEL,
                                   D_MODEL, 2 * D_MODEL, D_MODEL);

    rope_kernel<<<(BATCH * S_LEN * NUM_HEADS * 64) / 256, blk>>>(Q, K);

    static const int attn_smem = ATTN_SMEM_U32 * (int)sizeof(uint32_t);
    cudaFuncSetAttribute(attn_kernel, cudaFuncAttributeMaxDynamicSharedMemorySize,
                         attn_smem);
    attn_kernel<<<dim3(S_LEN / 128, BATCH * NUM_HEADS), blk, attn_smem>>>(Q, K, V, AO);

    tf32_gemm<true><<<grd, blk>>>(AO, wo, out, M_TOT, D_MODEL, D_MODEL,
                                  D_MODEL, D_MODEL, D_MODEL);
}